// round 2
// baseline (speedup 1.0000x reference)
#include <cuda_runtime.h>
#include <stdint.h>

// CutoutColor: out[n,c,h,w] = colors[n,c] if h in [top, top+28) && w in [left, left+28)
//              else x[n,c,h,w]
// Shapes: x [4096, 9, 84, 84] f32, colors [4096, 9] f32, tops/lefts [4096] i32.
// Memory-bound streaming kernel: float4-vectorized (W=84 = 21 * 4), 3D grid
// (x: hw-vec index, y: channel, z: sample).

#define N_   4096
#define C_   9
#define H_   84
#define W_   84
#define PATCH_ 28
#define W4_  (W_ / 4)        // 21
#define HW4_ (H_ * W4_)      // 1764

__global__ __launch_bounds__(256)
void cutout_color_kernel(const float4* __restrict__ x,
                         const float*  __restrict__ colors,
                         const int*    __restrict__ tops,
                         const int*    __restrict__ lefts,
                         float4*       __restrict__ out)
{
    const int i = blockIdx.x * blockDim.x + threadIdx.x;  // 0 .. HW4_-1
    if (i >= HW4_) return;

    const int n = blockIdx.z;
    const int c = blockIdx.y;

    const int h  = i / W4_;          // constant divisor -> mul-shift
    const int w0 = (i - h * W4_) * 4;

    // vec index into x/out: ((n*C + c) * HW4) + i  — fits in int32 (max ~65.0M)
    const int base = (n * C_ + c) * HW4_ + i;

    const int top  = tops[n];        // uniform per-z -> L1 broadcast
    const int left = lefts[n];

    const bool row_in = (h >= top) & (h < top + PATCH_);

    float4 v;
    if (row_in & (w0 >= left) & (w0 + 3 < left + PATCH_)) {
        // whole vector covered by the patch: skip the global read entirely
        const float col = colors[n * C_ + c];
        v = make_float4(col, col, col, col);
    } else {
        v = x[base];
        if (row_in) {
            const float col = colors[n * C_ + c];
            const int lo = left, hi = left + PATCH_;
            if (w0 + 0 >= lo && w0 + 0 < hi) v.x = col;
            if (w0 + 1 >= lo && w0 + 1 < hi) v.y = col;
            if (w0 + 2 >= lo && w0 + 2 < hi) v.z = col;
            if (w0 + 3 >= lo && w0 + 3 < hi) v.w = col;
        }
    }
    out[base] = v;
}

extern "C" void kernel_launch(void* const* d_in, const int* in_sizes, int n_in,
                              void* d_out, int out_size)
{
    const float4* x      = (const float4*)d_in[0];
    const float*  colors = (const float*) d_in[1];
    const int*    tops   = (const int*)   d_in[2];
    const int*    lefts  = (const int*)   d_in[3];
    float4*       out    = (float4*)      d_out;

    dim3 block(256);
    dim3 grid((HW4_ + 255) / 256, C_, N_);   // (7, 9, 4096)
    cutout_color_kernel<<<grid, block>>>(x, colors, tops, lefts, out);
}

// round 3
// speedup vs baseline: 1.2063x; 1.2063x over previous
#include <cuda_runtime.h>
#include <stdint.h>

// CutoutColor: out[n,c,h,w] = colors[n,c] if h in [top, top+28) && w in [left, left+28)
//              else x[n,c,h,w]
// x [4096, 9, 84, 84] f32, colors [4096, 9] f32, tops/lefts [4096] i32.
//
// R2: channel-fused variant. One thread = one spatial float4 vector for ALL
// 9 channels of one sample. Mask computed once; 9 independent LDG.128 are
// front-batched (MLP per thread = 9), then 9 STG.128. Full-inside-patch
// vectors skip all 9 global reads.

#define N_     4096
#define C_     9
#define H_     84
#define W_     84
#define PATCH_ 28
#define W4_    (W_ / 4)      // 21
#define HW4_   (H_ * W4_)    // 1764

__global__ __launch_bounds__(256)
void cutout_color_kernel(const float4* __restrict__ x,
                         const float*  __restrict__ colors,
                         const int*    __restrict__ tops,
                         const int*    __restrict__ lefts,
                         float4*       __restrict__ out)
{
    const int i = blockIdx.x * blockDim.x + threadIdx.x;  // spatial vec idx 0..HW4_-1
    if (i >= HW4_) return;

    const int n = blockIdx.y;

    const int h  = i / W4_;              // const-divisor -> mul/shift
    const int w0 = (i - h * W4_) * 4;

    const int top  = tops[n];            // uniform per-block -> L1 broadcast
    const int left = lefts[n];

    const bool row_in = (h >= top) & (h < top + PATCH_);
    const int  lo = left, hi = left + PATCH_;

    // vec index of (n, c=0, i); channel stride is HW4_ vecs. Max ~65.0M < 2^31.
    const int base = n * (C_ * HW4_) + i;

    const float* __restrict__ col = colors + n * C_;

    if (row_in & (w0 >= lo) & (w0 + 3 < hi)) {
        // whole vector inside the patch for every channel: pure writes
        #pragma unroll
        for (int c = 0; c < C_; ++c) {
            const float f = col[c];
            out[base + c * HW4_] = make_float4(f, f, f, f);
        }
        return;
    }

    // Front-batch all 9 independent loads (high MLP), then select+store.
    float4 v[C_];
    #pragma unroll
    for (int c = 0; c < C_; ++c)
        v[c] = x[base + c * HW4_];

    if (row_in) {
        const bool m0 = (w0 + 0 >= lo) & (w0 + 0 < hi);
        const bool m1 = (w0 + 1 >= lo) & (w0 + 1 < hi);
        const bool m2 = (w0 + 2 >= lo) & (w0 + 2 < hi);
        const bool m3 = (w0 + 3 >= lo) & (w0 + 3 < hi);
        #pragma unroll
        for (int c = 0; c < C_; ++c) {
            const float f = col[c];
            if (m0) v[c].x = f;
            if (m1) v[c].y = f;
            if (m2) v[c].z = f;
            if (m3) v[c].w = f;
        }
    }

    #pragma unroll
    for (int c = 0; c < C_; ++c)
        out[base + c * HW4_] = v[c];
}

extern "C" void kernel_launch(void* const* d_in, const int* in_sizes, int n_in,
                              void* d_out, int out_size)
{
    const float4* x      = (const float4*)d_in[0];
    const float*  colors = (const float*) d_in[1];
    const int*    tops   = (const int*)   d_in[2];
    const int*    lefts  = (const int*)   d_in[3];
    float4*       out    = (float4*)      d_out;

    dim3 block(256);
    dim3 grid((HW4_ + 255) / 256, N_);   // (7, 4096)
    cutout_color_kernel<<<grid, block>>>(x, colors, tops, lefts, out);
}

// round 6
// speedup vs baseline: 1.2121x; 1.0048x over previous
#include <cuda_runtime.h>
#include <stdint.h>

// CutoutColor: out[n,c,h,w] = colors[n,c] if h in [top, top+28) && w in [left, left+28)
//              else x[n,c,h,w]
// x [4096, 9, 84, 84] f32, colors [4096, 9] f32, tops/lefts [4096] i32.
//
// R3: same channel-fused structure as R2 (one thread = one spatial float4 for
// all 9 channels; mask computed once; 9 front-batched LDG.128; patch-interior
// read-skip), with cache-streaming (.cs, evict-first) hints on the bulk
// load/store streams: 2 GB streamed once through L2 has zero reuse, so
// evict-first lets LTS retire lines immediately instead of thrashing ways
// between the read and write-allocate streams.

#define N_     4096
#define C_     9
#define H_     84
#define W_     84
#define PATCH_ 28
#define W4_    (W_ / 4)      // 21
#define HW4_   (H_ * W4_)    // 1764

__global__ __launch_bounds__(256)
void cutout_color_kernel(const float4* __restrict__ x,
                         const float*  __restrict__ colors,
                         const int*    __restrict__ tops,
                         const int*    __restrict__ lefts,
                         float4*       __restrict__ out)
{
    const int i = blockIdx.x * blockDim.x + threadIdx.x;  // spatial vec idx 0..HW4_-1
    if (i >= HW4_) return;

    const int n = blockIdx.y;

    const int h  = i / W4_;              // const-divisor -> mul/shift
    const int w0 = (i - h * W4_) * 4;

    const int top  = tops[n];            // uniform per-block -> L1 broadcast
    const int left = lefts[n];

    const bool row_in = (h >= top) & (h < top + PATCH_);
    const int  lo = left, hi = left + PATCH_;

    // vec index of (n, c=0, i); channel stride is HW4_ vecs. Max ~65.0M < 2^31.
    const int base = n * (C_ * HW4_) + i;

    const float* __restrict__ col = colors + n * C_;

    if (row_in & (w0 >= lo) & (w0 + 3 < hi)) {
        // whole vector inside the patch for every channel: pure writes
        #pragma unroll
        for (int c = 0; c < C_; ++c) {
            const float f = col[c];
            __stcs(&out[base + c * HW4_], make_float4(f, f, f, f));
        }
        return;
    }

    // Front-batch all 9 independent streaming loads (high MLP), then select+store.
    float4 v[C_];
    #pragma unroll
    for (int c = 0; c < C_; ++c)
        v[c] = __ldcs(&x[base + c * HW4_]);

    if (row_in) {
        const bool m0 = (w0 + 0 >= lo) & (w0 + 0 < hi);
        const bool m1 = (w0 + 1 >= lo) & (w0 + 1 < hi);
        const bool m2 = (w0 + 2 >= lo) & (w0 + 2 < hi);
        const bool m3 = (w0 + 3 >= lo) & (w0 + 3 < hi);
        #pragma unroll
        for (int c = 0; c < C_; ++c) {
            const float f = col[c];
            if (m0) v[c].x = f;
            if (m1) v[c].y = f;
            if (m2) v[c].z = f;
            if (m3) v[c].w = f;
        }
    }

    #pragma unroll
    for (int c = 0; c < C_; ++c)
        __stcs(&out[base + c * HW4_], v[c]);
}

extern "C" void kernel_launch(void* const* d_in, const int* in_sizes, int n_in,
                              void* d_out, int out_size)
{
    const float4* x      = (const float4*)d_in[0];
    const float*  colors = (const float*) d_in[1];
    const int*    tops   = (const int*)   d_in[2];
    const int*    lefts  = (const int*)   d_in[3];
    float4*       out    = (float4*)      d_out;

    dim3 block(256);
    dim3 grid((HW4_ + 255) / 256, N_);   // (7, 4096)
    cutout_color_kernel<<<grid, block>>>(x, colors, tops, lefts, out);
}